// round 4
// baseline (speedup 1.0000x reference)
#include <cuda_runtime.h>
#include <math.h>

#define BB 8
#define CC_ 128
#define HH 128
#define WW 128
#define LL (HH*WW)
#define MID 32

// ---- device scratch (allocation-free rule: __device__ globals) ----
__device__ __align__(16) float g_Y[BB*CC_*LL];     // projected pre-BN output (b,c,L)
__device__ __align__(16) float g_M2[416*128];      // combined matrix, [k][o] layout
__device__ float g_cvec[128];
__device__ float g_gap[BB*128];
__device__ float g_a0[BB*128], g_a1[BB*128], g_a2[BB*128];
__device__ float g_pvec[BB*MID];
__device__ __align__(16) float g_t[BB*LL];
__device__ float g_sum[128], g_ssq[128];
__device__ float g_scale[128], g_shift[128];

// ---- packed f32x2 helpers (sm_103a FFMA2 path, PTX-only) ----
__device__ __forceinline__ unsigned long long f2pk(float lo, float hi) {
    unsigned long long r;
    asm("mov.b64 %0, {%1, %2};" : "=l"(r) : "f"(lo), "f"(hi));
    return r;
}
__device__ __forceinline__ void f2fma(unsigned long long& d, unsigned long long a,
                                      unsigned long long b) {
    asm("fma.rn.f32x2 %0, %1, %2, %0;" : "+l"(d) : "l"(a), "l"(b));
}
__device__ __forceinline__ void f2unpk(float& lo, float& hi, unsigned long long v) {
    asm("mov.b64 {%0, %1}, %2;" : "=f"(lo), "=f"(hi) : "l"(v));
}

// ---- zero BN accumulators (graph replays must be deterministic) ----
__global__ void k_zero() {
    int t = threadIdx.x;
    if (t < 128) { g_sum[t] = 0.f; g_ssq[t] = 0.f; }
}

// ---- per (b,c) plane mean ----
__global__ void k_gap(const float* __restrict__ x) {
    int c = blockIdx.x, b = blockIdx.y;
    const float* p = x + ((size_t)(b*CC_ + c))*LL;
    float s = 0.f;
    for (int i = threadIdx.x; i < LL; i += 256) s += p[i];
    __shared__ float red[256];
    red[threadIdx.x] = s; __syncthreads();
    for (int off = 128; off > 0; off >>= 1) {
        if (threadIdx.x < off) red[threadIdx.x] += red[threadIdx.x + off];
        __syncthreads();
    }
    if (threadIdx.x == 0) g_gap[b*CC_ + c] = red[0] * (1.0f/LL);
}

// ---- per-batch derived vectors: g, a0/a1/a2, pvec ----
__global__ void k_gvec(const float* __restrict__ wco, const float* __restrict__ wci,
                       const float* __restrict__ wcd, const float* __restrict__ wm1) {
    int b = blockIdx.x, c = threadIdx.x;
    __shared__ float gs[128], rs[128], red[128];
    float gv = g_gap[b*CC_ + c];
    red[c] = gv*gv; __syncthreads();
    for (int off = 64; off > 0; off >>= 1) {
        if (c < off) red[c] += red[c + off];
        __syncthreads();
    }
    float nrm = fmaxf(sqrtf(red[0]), 1e-12f);
    gv /= nrm;
    gs[c] = gv; __syncthreads();
    float rv = 0.f;
    for (int o = 0; o < CC_; o++) rv += wco[o*CC_ + c] * gs[o];
    rs[c] = rv; __syncthreads();
    float a0 = 0.f, a1 = 0.f, a2 = 0.f;
    for (int j = 0; j < CC_; j++) {
        float rr = rs[j];
        float wi = wci[j*CC_ + c];
        a0 += wi * wcd[j*3+0] * rr;
        a1 += wi * wcd[j*3+1] * rr;
        a2 += wi * wcd[j*3+2] * rr;
    }
    g_a0[b*CC_+c] = a0; g_a1[b*CC_+c] = a1; g_a2[b*CC_+c] = a2;
    if (c < MID) {
        float pm = 0.f;
        for (int j = 0; j < CC_; j++) pm += wm1[c*CC_ + j] * gs[j];
        g_pvec[b*MID + c] = pm;
    }
}

// ---- fold all linear ops into one [416 x 128] matrix ----
// In layout per channel j: k=3j -> S_j, k=3j+1 -> x_j, k=3j+2 -> dsum_j ; k=384..415 -> silu vec
__global__ void k_mat(const float* __restrict__ wp,  const float* __restrict__ wso,
                      const float* __restrict__ wsi, const float* __restrict__ wsd,
                      const float* __restrict__ wm2, const float* __restrict__ bm2,
                      const float* __restrict__ dwp) {
    int o = blockIdx.x, tid = threadIdx.x;
    __shared__ float t1[128];
    float t = 0.f;
    for (int k = 0; k < CC_; k++) t += wp[o*CC_ + k] * wso[k*CC_ + tid];
    t1[tid] = t; __syncthreads();
    int c = tid;
    float av = 0.f, bv = 0.f;
    for (int m = 0; m < CC_; m++) {
        float wm = wsi[m*CC_ + c];
        av += t1[m] * (wsd[m*3+0] + wsd[m*3+2]) * wm;
        bv += t1[m] *  wsd[m*3+1] * wm;
    }
    float wpoc = wp[o*CC_ + c];
    float dw = *dwp;
    g_M2[(3*c+0)*128 + o] = 0.25f * av;          // A' applied to S
    g_M2[(3*c+1)*128 + o] = bv + wpoc;           // B (spatial-center + identity-from-diff)
    g_M2[(3*c+2)*128 + o] = 0.25f * dw * wpoc;   // C applied to raw abs-diff sum
    if (c < MID) {
        float dv = 0.f;
        for (int k = 0; k < CC_; k++) dv += wp[o*CC_ + k] * wm2[k*MID + c];
        g_M2[(384 + c)*128 + o] = dv;            // D = Wp @ W_mlp2
    }
    if (tid == 0) {
        float cv = 0.f;
        for (int k = 0; k < CC_; k++) cv += wp[o*CC_ + k] * bm2[k];
        g_cvec[o] = cv;
    }
}

// ---- scalar field t[b][p] (channel-branch rank-1 projection) ----
__global__ void k_t(const float* __restrict__ x) {
    int r = blockIdx.x, b = blockIdx.y, cc = threadIdx.x;
    int p = r*WW + cc;
    const float* xb = x + (size_t)b*CC_*LL;
    const float* a0 = g_a0 + b*CC_;
    const float* a1 = g_a1 + b*CC_;
    const float* a2 = g_a2 + b*CC_;
    bool hm = (p > 0), hp = (p < LL-1);
    float t = 0.f;
    for (int c = 0; c < CC_; c++) {
        const float* xc = xb + (size_t)c*LL + p;
        float xv = xc[0];
        float xm = hm ? xc[-1] : 0.f;
        float xp = hp ? xc[1]  : 0.f;
        t += a0[c]*xm + a1[c]*xv + a2[c]*xp;
    }
    g_t[b*LL + p] = t;
}

// ---- fused main kernel: one block per (image row r, batch b) ----
// computes y_proj for 128 out-channels x 128 positions, accumulates BN stats
#define SM_FLOATS (6144 + 6336 + 6336 + 128 + 128 + 128)

// one rank-1 FFMA2 step: 8 outs (ty) x 8 positions (tx), packed pairs
__device__ __forceinline__ void rank1_step(unsigned long long acc[8][4],
                                           const float* mrow, const float* irow) {
    float4 m0 = *(const float4*)mrow, m1 = *(const float4*)(mrow+4);
    float4 i0 = *(const float4*)irow, i1 = *(const float4*)(irow+4);
    unsigned long long iv[4] = { f2pk(i0.x,i0.y), f2pk(i0.z,i0.w),
                                 f2pk(i1.x,i1.y), f2pk(i1.z,i1.w) };
    unsigned long long mv[8] = { f2pk(m0.x,m0.x), f2pk(m0.y,m0.y),
                                 f2pk(m0.z,m0.z), f2pk(m0.w,m0.w),
                                 f2pk(m1.x,m1.x), f2pk(m1.y,m1.y),
                                 f2pk(m1.z,m1.z), f2pk(m1.w,m1.w) };
    #pragma unroll
    for (int a = 0; a < 8; a++)
        #pragma unroll
        for (int j = 0; j < 4; j++)
            f2fma(acc[a][j], mv[a], iv[j]);
}

__global__ void __launch_bounds__(256, 2) k_main(const float* __restrict__ x,
                                                 const float* __restrict__ bm1) {
    extern __shared__ float sm[];
    float* xs   = sm;                 // 16 ch * 3 rows * 128 cols
    float* Ins  = xs   + 6144;        // 48 x 132 (stride-padded)
    float* Msh  = Ins  + 6336;        // 48 x 132
    float* tv   = Msh  + 6336;        // 128
    float* bsum = tv   + 128;         // 128
    float* bssq = bsum + 128;         // 128

    int r = blockIdx.x, b = blockIdx.y;
    int tid = threadIdx.x;
    int tx = tid & 15, ty = tid >> 4;

    unsigned long long acc[8][4];
    unsigned long long z0 = f2pk(0.f, 0.f);
    #pragma unroll
    for (int a = 0; a < 8; a++)
        #pragma unroll
        for (int j = 0; j < 4; j++) acc[a][j] = z0;

    int rM = (r > 0)   ? r-1 : 127;   // prev row in column-scan wrap
    int rP = (r < 127) ? r+1 : 0;     // next row in column-scan wrap
    const float* xb = x + (size_t)b*CC_*LL;

    if (tid < 128) {
        tv[tid] = g_t[b*LL + r*WW + tid];
        bsum[tid] = 0.f; bssq[tid] = 0.f;
    }

    for (int ch = 0; ch < 8; ch++) {
        int c0 = ch*16;
        // stage x slab (16 channels x rows {rM,r,rP}) and matrix chunk
        for (int i = tid; i < 1536; i += 256) {
            int pair = i >> 5, col4 = i & 31;
            int ci = pair/3, rsel = pair%3;
            int row = (rsel == 0) ? rM : ((rsel == 1) ? r : rP);
            float4 v = *(const float4*)(xb + ((size_t)(c0+ci)*HH + row)*WW + col4*4);
            *(float4*)(xs + (ci*3 + rsel)*128 + col4*4) = v;
        }
        for (int i = tid; i < 1536; i += 256) {
            int kk = i >> 5, col4 = i & 31;
            float4 v = *(const float4*)(g_M2 + (ch*48 + kk)*128 + col4*4);
            *(float4*)(Msh + kk*132 + col4*4) = v;
        }
        __syncthreads();
        // build stencil inputs S / x / dsum
        for (int i = tid; i < 2048; i += 256) {
            int ci = i >> 7, cc = i & 127;
            const float* xr = xs + ci*3*128;   // [0]=rM row, [128]=r row, [256]=rP row
            float xc = xr[128 + cc];
            // sequence neighbors (row scan +/-1, col scan +/-1) with wrap & global-end zero
            float prev = (cc > 0)   ? xr[128 + cc - 1] : ((r == 0)   ? 0.f : xr[127]);
            float nxt  = (cc < 127) ? xr[128 + cc + 1] : ((r == 127) ? 0.f : xr[256]);
            float cp   = (r > 0)    ? xr[cc]        : ((cc > 0)   ? xr[cc - 1]       : 0.f);
            float cn   = (r < 127)  ? xr[256 + cc]  : ((cc < 127) ? xr[256 + cc + 1] : 0.f);
            float S = prev + nxt + cp + cn;
            // reflect-pad abs-diff stencil
            float l2 = (cc == 0)   ? xr[128 + 1]   : xr[128 + cc - 1];
            float r2 = (cc == 127) ? xr[128 + 126] : xr[128 + cc + 1];
            float u2 = (r == 0)    ? xr[256 + cc]  : xr[cc];          // reflect row1 == rP when r==0
            float d2 = (r == 127)  ? xr[cc]        : xr[256 + cc];    // reflect row126 == rM when r==127
            float ds = fabsf(xc-l2) + fabsf(xc-r2) + fabsf(xc-u2) + fabsf(xc-d2);
            Ins[(3*ci+0)*132 + cc] = S;
            Ins[(3*ci+1)*132 + cc] = xc;
            Ins[(3*ci+2)*132 + cc] = ds;
        }
        __syncthreads();
        // 48-step rank-1 updates (8x8 register tile, packed f32x2 FMAs)
        #pragma unroll 4
        for (int k = 0; k < 48; k++)
            rank1_step(acc, Msh + k*132 + ty*8, Ins + k*132 + tx*8);
        __syncthreads();
    }

    // MLP chunk: sv = silu(pvec*t + b1), apply D
    for (int i = tid; i < 4096; i += 256) {
        int m = i >> 7, cc = i & 127;
        float z = g_pvec[b*MID + m]*tv[cc] + bm1[m];
        Ins[m*132 + cc] = z / (1.f + expf(-z));
    }
    for (int i = tid; i < 1024; i += 256) {
        int kk = i >> 5, col4 = i & 31;
        *(float4*)(Msh + kk*132 + col4*4) = *(const float4*)(g_M2 + (384+kk)*128 + col4*4);
    }
    __syncthreads();
    #pragma unroll 4
    for (int k = 0; k < 32; k++)
        rank1_step(acc, Msh + k*132 + ty*8, Ins + k*132 + tx*8);

    // epilogue: +cvec, write g_Y, BN partial stats
    #pragma unroll
    for (int a = 0; a < 8; a++) {
        int o = ty*8 + a;
        float cv = g_cvec[o];
        float s = 0.f, ss = 0.f;
        float vals[8];
        #pragma unroll
        for (int j = 0; j < 4; j++) {
            float lo, hi;
            f2unpk(lo, hi, acc[a][j]);
            vals[2*j]   = lo + cv;
            vals[2*j+1] = hi + cv;
        }
        #pragma unroll
        for (int q = 0; q < 8; q++) { s += vals[q]; ss += vals[q]*vals[q]; }
        float4* dst = (float4*)(g_Y + ((size_t)(b*CC_ + o))*LL + r*WW + tx*8);
        dst[0] = make_float4(vals[0], vals[1], vals[2], vals[3]);
        dst[1] = make_float4(vals[4], vals[5], vals[6], vals[7]);
        atomicAdd(&bsum[o], s);
        atomicAdd(&bssq[o], ss);
    }
    __syncthreads();
    if (tid < 128) {
        atomicAdd(&g_sum[tid], bsum[tid]);
        atomicAdd(&g_ssq[tid], bssq[tid]);
    }
}

// ---- BN stats finalize ----
__global__ void k_stats(const float* __restrict__ gamma, const float* __restrict__ beta) {
    int c = threadIdx.x;
    float n = (float)(BB*LL);
    float mu = g_sum[c] / n;
    float var = g_ssq[c] / n - mu*mu;
    float rsd = rsqrtf(var + 1e-5f);
    float sc = rsd * gamma[c];
    g_scale[c] = sc;
    g_shift[c] = beta[c] - mu*sc;
}

// ---- normalize + write output ----
__global__ void k_final(float* __restrict__ out) {
    int total = BB*CC_*LL/4;
    for (int idx = blockIdx.x*blockDim.x + threadIdx.x; idx < total;
         idx += gridDim.x*blockDim.x) {
        int c = ((idx*4) >> 14) & 127;
        float sc = g_scale[c], sh = g_shift[c];
        float4 v = ((const float4*)g_Y)[idx];
        v.x = v.x*sc + sh; v.y = v.y*sc + sh;
        v.z = v.z*sc + sh; v.w = v.w*sc + sh;
        ((float4*)out)[idx] = v;
    }
}

extern "C" void kernel_launch(void* const* d_in, const int* in_sizes, int n_in,
                              void* d_out, int out_size) {
    const float* x     = (const float*)d_in[0];
    const float* wsi   = (const float*)d_in[1];
    const float* wsd   = (const float*)d_in[2];
    const float* wso   = (const float*)d_in[3];
    const float* wci   = (const float*)d_in[4];
    const float* wcd   = (const float*)d_in[5];
    const float* wco   = (const float*)d_in[6];
    const float* wm1   = (const float*)d_in[7];
    const float* bm1   = (const float*)d_in[8];
    const float* wm2   = (const float*)d_in[9];
    const float* bm2   = (const float*)d_in[10];
    const float* dwp   = (const float*)d_in[11];
    const float* gamma = (const float*)d_in[12];
    const float* beta  = (const float*)d_in[13];
    const float* wp    = (const float*)d_in[14];

    cudaFuncSetAttribute(k_main, cudaFuncAttributeMaxDynamicSharedMemorySize,
                         SM_FLOATS * (int)sizeof(float));

    k_zero<<<1, 128>>>();
    k_gap<<<dim3(128, 8), 256>>>(x);
    k_gvec<<<8, 128>>>(wco, wci, wcd, wm1);
    k_mat<<<128, 128>>>(wp, wso, wsi, wsd, wm2, bm2, dwp);
    k_t<<<dim3(128, 8), 128>>>(x);
    k_main<<<dim3(128, 8), 256, SM_FLOATS * (int)sizeof(float)>>>(x, bm1);
    k_stats<<<1, 128>>>(gamma, beta);
    k_final<<<4096, 256>>>((float*)d_out);
}

// round 10
// speedup vs baseline: 1.0380x; 1.0380x over previous
#include <cuda_runtime.h>
#include <math.h>

#define BB 8
#define CC_ 128
#define HH 128
#define WW 128
#define LL (HH*WW)
#define MID 32

// ---- device scratch (allocation-free rule: __device__ globals) ----
__device__ __align__(16) float g_Y[BB*CC_*LL];     // projected pre-BN output (b,c,L)
__device__ __align__(16) float g_M2[416*128];      // combined matrix, [k][o] layout
__device__ float g_cvec[128];
__device__ float g_gap[BB*128];
__device__ float g_a0[BB*128], g_a1[BB*128], g_a2[BB*128];
__device__ float g_pvec[BB*MID];
__device__ float g_sum[128], g_ssq[128];
__device__ float g_scale[128], g_shift[128];

// ---- packed f32x2 helpers (sm_103a FFMA2 path, PTX-only) ----
__device__ __forceinline__ unsigned long long f2pk(float lo, float hi) {
    unsigned long long r;
    asm("mov.b64 %0, {%1, %2};" : "=l"(r) : "f"(lo), "f"(hi));
    return r;
}
__device__ __forceinline__ void f2fma(unsigned long long& d, unsigned long long a,
                                      unsigned long long b) {
    asm("fma.rn.f32x2 %0, %1, %2, %0;" : "+l"(d) : "l"(a), "l"(b));
}
__device__ __forceinline__ void f2unpk(float& lo, float& hi, unsigned long long v) {
    asm("mov.b64 {%0, %1}, %2;" : "=f"(lo), "=f"(hi) : "l"(v));
}

// ---- zero BN accumulators (graph replays must be deterministic) ----
__global__ void k_zero() {
    int t = threadIdx.x;
    if (t < 128) { g_sum[t] = 0.f; g_ssq[t] = 0.f; }
}

// ---- per (b,c) plane mean ----
__global__ void k_gap(const float* __restrict__ x) {
    int c = blockIdx.x, b = blockIdx.y;
    const float* p = x + ((size_t)(b*CC_ + c))*LL;
    float s = 0.f;
    for (int i = threadIdx.x; i < LL; i += 256) s += p[i];
    __shared__ float red[256];
    red[threadIdx.x] = s; __syncthreads();
    for (int off = 128; off > 0; off >>= 1) {
        if (threadIdx.x < off) red[threadIdx.x] += red[threadIdx.x + off];
        __syncthreads();
    }
    if (threadIdx.x == 0) g_gap[b*CC_ + c] = red[0] * (1.0f/LL);
}

// ---- per-batch derived vectors: g, a0/a1/a2, pvec ----
__global__ void k_gvec(const float* __restrict__ wco, const float* __restrict__ wci,
                       const float* __restrict__ wcd, const float* __restrict__ wm1) {
    int b = blockIdx.x, c = threadIdx.x;
    __shared__ float gs[128], rs[128], red[128];
    float gv = g_gap[b*CC_ + c];
    red[c] = gv*gv; __syncthreads();
    for (int off = 64; off > 0; off >>= 1) {
        if (c < off) red[c] += red[c + off];
        __syncthreads();
    }
    float nrm = fmaxf(sqrtf(red[0]), 1e-12f);
    gv /= nrm;
    gs[c] = gv; __syncthreads();
    float rv = 0.f;
    #pragma unroll 8
    for (int o = 0; o < CC_; o++) rv += wco[o*CC_ + c] * gs[o];
    rs[c] = rv; __syncthreads();
    float a0 = 0.f, a1 = 0.f, a2 = 0.f;
    #pragma unroll 4
    for (int j = 0; j < CC_; j++) {
        float rr = rs[j];
        float wi = wci[j*CC_ + c];
        a0 += wi * wcd[j*3+0] * rr;
        a1 += wi * wcd[j*3+1] * rr;
        a2 += wi * wcd[j*3+2] * rr;
    }
    g_a0[b*CC_+c] = a0; g_a1[b*CC_+c] = a1; g_a2[b*CC_+c] = a2;
    if (c < MID) {
        float pm = 0.f;
        #pragma unroll 8
        for (int j = 0; j < CC_; j++) pm += wm1[c*CC_ + j] * gs[j];
        g_pvec[b*MID + c] = pm;
    }
}

// ---- fold all linear ops into one [416 x 128] matrix ----
// ILP via 4-way split accumulators (k_mat was latency-bound at 44us, occ 5%)
__global__ void k_mat(const float* __restrict__ wp,  const float* __restrict__ wso,
                      const float* __restrict__ wsi, const float* __restrict__ wsd,
                      const float* __restrict__ wm2, const float* __restrict__ bm2,
                      const float* __restrict__ dwp) {
    int o = blockIdx.x, tid = threadIdx.x;
    __shared__ float t1[128];
    __shared__ float wps[128];
    __shared__ float u[128], v[128];
    // stage wp row + dwconv taps
    wps[tid] = wp[o*CC_ + tid];
    u[tid] = wsd[tid*3+0] + wsd[tid*3+2];
    v[tid] = wsd[tid*3+1];
    __syncthreads();
    float s0=0.f, s1=0.f, s2=0.f, s3=0.f;
    #pragma unroll 8
    for (int k = 0; k < CC_; k += 4) {
        s0 += wps[k+0] * wso[(k+0)*CC_ + tid];
        s1 += wps[k+1] * wso[(k+1)*CC_ + tid];
        s2 += wps[k+2] * wso[(k+2)*CC_ + tid];
        s3 += wps[k+3] * wso[(k+3)*CC_ + tid];
    }
    t1[tid] = (s0+s1)+(s2+s3); __syncthreads();
    int c = tid;
    float av0=0.f, av1=0.f, bv0=0.f, bv1=0.f;
    #pragma unroll 8
    for (int m = 0; m < CC_; m += 2) {
        float w0 = wsi[(m+0)*CC_ + c], w1 = wsi[(m+1)*CC_ + c];
        float tu0 = t1[m+0], tu1 = t1[m+1];
        av0 += tu0 * u[m+0] * w0;
        bv0 += tu0 * v[m+0] * w0;
        av1 += tu1 * u[m+1] * w1;
        bv1 += tu1 * v[m+1] * w1;
    }
    float wpoc = wps[c];
    float dw = *dwp;
    g_M2[(3*c+0)*128 + o] = 0.25f * (av0+av1);       // A' applied to S
    g_M2[(3*c+1)*128 + o] = (bv0+bv1) + wpoc;        // B (spatial-center + identity)
    g_M2[(3*c+2)*128 + o] = 0.25f * dw * wpoc;       // C applied to abs-diff sum
    if (c < MID) {
        float d0=0.f, d1=0.f, d2=0.f, d3=0.f;
        #pragma unroll 8
        for (int k = 0; k < CC_; k += 4) {
            d0 += wps[k+0] * wm2[(k+0)*MID + c];
            d1 += wps[k+1] * wm2[(k+1)*MID + c];
            d2 += wps[k+2] * wm2[(k+2)*MID + c];
            d3 += wps[k+3] * wm2[(k+3)*MID + c];
        }
        g_M2[(384 + c)*128 + o] = (d0+d1)+(d2+d3);   // D = Wp @ W_mlp2
    }
    if (tid == 0) {
        float cv = 0.f;
        #pragma unroll 8
        for (int k = 0; k < CC_; k++) cv += wps[k] * bm2[k];
        g_cvec[o] = cv;
    }
}

// ---- fused main kernel: one block per (image row r, batch b) ----
// computes y_proj for 128 out-channels x 128 positions, accumulates BN stats,
// and computes the channel-branch scalar field t inline (k_t fused away)
#define SM_FLOATS (6144 + 6336 + 6336 + 128 + 128 + 128)

// one rank-1 FFMA2 step: 8 outs (ty) x 8 positions (tx), packed pairs.
// register-slimmed: packed multiplier lives one 'a' iteration only (~86 live regs)
__device__ __forceinline__ void rank1_step(unsigned long long acc[8][4],
                                           const float* mrow, const float* irow) {
    float4 i0 = *(const float4*)irow, i1 = *(const float4*)(irow+4);
    unsigned long long iv0 = f2pk(i0.x,i0.y), iv1 = f2pk(i0.z,i0.w);
    unsigned long long iv2 = f2pk(i1.x,i1.y), iv3 = f2pk(i1.z,i1.w);
    float4 m0 = *(const float4*)mrow, m1 = *(const float4*)(mrow+4);
    float mv[8] = {m0.x,m0.y,m0.z,m0.w,m1.x,m1.y,m1.z,m1.w};
    #pragma unroll
    for (int a = 0; a < 8; a++) {
        unsigned long long mp = f2pk(mv[a], mv[a]);
        f2fma(acc[a][0], mp, iv0);
        f2fma(acc[a][1], mp, iv1);
        f2fma(acc[a][2], mp, iv2);
        f2fma(acc[a][3], mp, iv3);
    }
}

__global__ void __launch_bounds__(256, 2) k_main(const float* __restrict__ x,
                                                 const float* __restrict__ bm1) {
    extern __shared__ float sm[];
    float* xs   = sm;                 // 16 ch * 3 rows * 128 cols
    float* Ins  = xs   + 6144;        // 48 x 132 (stride-padded)
    float* Msh  = Ins  + 6336;        // 48 x 132
    float* tv   = Msh  + 6336;        // 128 (t field, accumulated via atomics)
    float* bsum = tv   + 128;         // 128
    float* bssq = bsum + 128;         // 128

    int r = blockIdx.x, b = blockIdx.y;
    int tid = threadIdx.x;
    int tx = tid & 15, ty = tid >> 4;
    int ccs = tid & 127;              // fixed column owned by this thread in Ins loop

    unsigned long long acc[8][4];
    unsigned long long z0 = f2pk(0.f, 0.f);
    #pragma unroll
    for (int a = 0; a < 8; a++)
        #pragma unroll
        for (int j = 0; j < 4; j++) acc[a][j] = z0;

    int rM = (r > 0)   ? r-1 : 127;   // prev row in column-scan wrap
    int rP = (r < 127) ? r+1 : 0;     // next row in column-scan wrap
    const float* xb = x + (size_t)b*CC_*LL;
    const float* a0g = g_a0 + b*CC_;
    const float* a1g = g_a1 + b*CC_;
    const float* a2g = g_a2 + b*CC_;

    if (tid < 128) { tv[tid] = 0.f; bsum[tid] = 0.f; bssq[tid] = 0.f; }

    float treg = 0.f;                 // per-thread partial of t[b][r*W + ccs]

    for (int ch = 0; ch < 8; ch++) {
        int c0 = ch*16;
        // stage x slab (16 channels x rows {rM,r,rP}) and matrix chunk
        for (int i = tid; i < 1536; i += 256) {
            int pair = i >> 5, col4 = i & 31;
            int ci = pair/3, rsel = pair%3;
            int row = (rsel == 0) ? rM : ((rsel == 1) ? r : rP);
            float4 v = *(const float4*)(xb + ((size_t)(c0+ci)*HH + row)*WW + col4*4);
            *(float4*)(xs + (ci*3 + rsel)*128 + col4*4) = v;
        }
        for (int i = tid; i < 1536; i += 256) {
            int kk = i >> 5, col4 = i & 31;
            float4 v = *(const float4*)(g_M2 + (ch*48 + kk)*128 + col4*4);
            *(float4*)(Msh + kk*132 + col4*4) = v;
        }
        __syncthreads();
        // build stencil inputs S / x / dsum ; fold t accumulation in (cc==ccs always)
        for (int i = tid; i < 2048; i += 256) {
            int ci = i >> 7, cc = i & 127;   // cc == ccs (stride 256 preserves low 7 bits)
            int c = c0 + ci;
            const float* xr = xs + ci*3*128;   // [0]=rM row, [128]=r row, [256]=rP row
            float xc = xr[128 + cc];
            // sequence neighbors (row scan +/-1, col scan +/-1) with wrap & global-end zero
            float prev = (cc > 0)   ? xr[128 + cc - 1] : ((r == 0)   ? 0.f : xr[127]);
            float nxt  = (cc < 127) ? xr[128 + cc + 1] : ((r == 127) ? 0.f : xr[256]);
            float cp   = (r > 0)    ? xr[cc]        : ((cc > 0)   ? xr[cc - 1]       : 0.f);
            float cn   = (r < 127)  ? xr[256 + cc]  : ((cc < 127) ? xr[256 + cc + 1] : 0.f);
            float S = prev + nxt + cp + cn;
            // channel-branch dwconv projection (same zero-at-global-ends convention)
            treg += a0g[c]*prev + a1g[c]*xc + a2g[c]*nxt;
            // reflect-pad abs-diff stencil
            float l2 = (cc == 0)   ? xr[128 + 1]   : xr[128 + cc - 1];
            float r2 = (cc == 127) ? xr[128 + 126] : xr[128 + cc + 1];
            float u2 = (r == 0)    ? xr[256 + cc]  : xr[cc];          // reflect: row1 when r==0
            float d2 = (r == 127)  ? xr[cc]        : xr[256 + cc];    // reflect: row126 when r==127
            float ds = fabsf(xc-l2) + fabsf(xc-r2) + fabsf(xc-u2) + fabsf(xc-d2);
            Ins[(3*ci+0)*132 + cc] = S;
            Ins[(3*ci+1)*132 + cc] = xc;
            Ins[(3*ci+2)*132 + cc] = ds;
        }
        __syncthreads();
        // 48-step rank-1 updates (8x8 register tile, packed f32x2 FMAs)
        #pragma unroll 4
        for (int k = 0; k < 48; k++)
            rank1_step(acc, Msh + k*132 + ty*8, Ins + k*132 + tx*8);
        __syncthreads();
    }

    // finalize t field (2 threads per column)
    atomicAdd(&tv[ccs], treg);
    __syncthreads();

    // MLP chunk: sv = silu(pvec*t + b1), apply D
    for (int i = tid; i < 4096; i += 256) {
        int m = i >> 7, cc = i & 127;
        float z = g_pvec[b*MID + m]*tv[cc] + bm1[m];
        Ins[m*132 + cc] = z / (1.f + expf(-z));
    }
    for (int i = tid; i < 1024; i += 256) {
        int kk = i >> 5, col4 = i & 31;
        *(float4*)(Msh + kk*132 + col4*4) = *(const float4*)(g_M2 + (384+kk)*128 + col4*4);
    }
    __syncthreads();
    #pragma unroll 4
    for (int k = 0; k < 32; k++)
        rank1_step(acc, Msh + k*132 + ty*8, Ins + k*132 + tx*8);

    // epilogue: +cvec, write g_Y, BN partial stats
    #pragma unroll
    for (int a = 0; a < 8; a++) {
        int o = ty*8 + a;
        float cv = g_cvec[o];
        float s = 0.f, ss = 0.f;
        float vals[8];
        #pragma unroll
        for (int j = 0; j < 4; j++) {
            float lo, hi;
            f2unpk(lo, hi, acc[a][j]);
            vals[2*j]   = lo + cv;
            vals[2*j+1] = hi + cv;
        }
        #pragma unroll
        for (int q = 0; q < 8; q++) { s += vals[q]; ss += vals[q]*vals[q]; }
        float4* dst = (float4*)(g_Y + ((size_t)(b*CC_ + o))*LL + r*WW + tx*8);
        dst[0] = make_float4(vals[0], vals[1], vals[2], vals[3]);
        dst[1] = make_float4(vals[4], vals[5], vals[6], vals[7]);
        atomicAdd(&bsum[o], s);
        atomicAdd(&bssq[o], ss);
    }
    __syncthreads();
    if (tid < 128) {
        atomicAdd(&g_sum[tid], bsum[tid]);
        atomicAdd(&g_ssq[tid], bssq[tid]);
    }
}

// ---- BN stats finalize ----
__global__ void k_stats(const float* __restrict__ gamma, const float* __restrict__ beta) {
    int c = threadIdx.x;
    float n = (float)(BB*LL);
    float mu = g_sum[c] / n;
    float var = g_ssq[c] / n - mu*mu;
    float rsd = rsqrtf(var + 1e-5f);
    float sc = rsd * gamma[c];
    g_scale[c] = sc;
    g_shift[c] = beta[c] - mu*sc;
}

// ---- normalize + write output ----
__global__ void k_final(float* __restrict__ out) {
    int total = BB*CC_*LL/4;
    for (int idx = blockIdx.x*blockDim.x + threadIdx.x; idx < total;
         idx += gridDim.x*blockDim.x) {
        int c = ((idx*4) >> 14) & 127;
        float sc = g_scale[c], sh = g_shift[c];
        float4 v = ((const float4*)g_Y)[idx];
        v.x = v.x*sc + sh; v.y = v.y*sc + sh;
        v.z = v.z*sc + sh; v.w = v.w*sc + sh;
        ((float4*)out)[idx] = v;
    }
}

extern "C" void kernel_launch(void* const* d_in, const int* in_sizes, int n_in,
                              void* d_out, int out_size) {
    const float* x     = (const float*)d_in[0];
    const float* wsi   = (const float*)d_in[1];
    const float* wsd   = (const float*)d_in[2];
    const float* wso   = (const float*)d_in[3];
    const float* wci   = (const float*)d_in[4];
    const float* wcd   = (const float*)d_in[5];
    const float* wco   = (const float*)d_in[6];
    const float* wm1   = (const float*)d_in[7];
    const float* bm1   = (const float*)d_in[8];
    const float* wm2   = (const float*)d_in[9];
    const float* bm2   = (const float*)d_in[10];
    const float* dwp   = (const float*)d_in[11];
    const float* gamma = (const float*)d_in[12];
    const float* beta  = (const float*)d_in[13];
    const float* wp    = (const float*)d_in[14];

    cudaFuncSetAttribute(k_main, cudaFuncAttributeMaxDynamicSharedMemorySize,
                         SM_FLOATS * (int)sizeof(float));

    k_zero<<<1, 128>>>();
    k_gap<<<dim3(128, 8), 256>>>(x);
    k_gvec<<<8, 128>>>(wco, wci, wcd, wm1);
    k_mat<<<128, 128>>>(wp, wso, wsi, wsd, wm2, bm2, dwp);
    k_main<<<dim3(128, 8), 256, SM_FLOATS * (int)sizeof(float)>>>(x, bm1);
    k_stats<<<1, 128>>>(gamma, beta);
    k_final<<<4096, 256>>>((float*)d_out);
}